// round 15
// baseline (speedup 1.0000x reference)
#include <cuda_runtime.h>
#include <cuda_fp16.h>

// ===================== problem constants =====================
#define KDIM    256            // x row: c*64+d
#define NDIM    512            // t*32+o
#define MTILE   32
#define THREADS 256
#define TPC     8              // tokens per CTA (N half)

// ===================== smem layout =====================
#define PITCH   144                        // 64 fp16 (128B) + 16B pad (validated conflict-free)
#define TTOK    (32 * PITCH)               // 4608 per token sub-tile (32 rows)
#define YBUF    (TPC * TTOK)               // 36864 per y buffer; Wg staged here at init
#define SM_Y    0                          // 2 buffers: 73728
#define SM_WMD  (2 * YBUF)                 // dup-packed Wm: 8*4 u64 = 256
#define SMEM_TOTAL (SM_WMD + 256 + 128)    // 74112 (x2 CTA/SM = 148224 < 227KB)

typedef unsigned long long u64;

// ===================== PTX helpers (validated mappings) =====================
__device__ __forceinline__ unsigned smem_u32(const void* p) {
    unsigned a;
    asm("{ .reg .u64 t; cvta.to.shared.u64 t, %1; cvt.u32.u64 %0, t; }" : "=r"(a) : "l"(p));
    return a;
}
__device__ __forceinline__ u64 ffma2(u64 a, u64 b, u64 c) {
    u64 d;
    asm("fma.rn.f32x2 %0, %1, %2, %3;" : "=l"(d) : "l"(a), "l"(b), "l"(c));
    return d;
}
__device__ __forceinline__ u64 fmul2(u64 a, u64 b) {
    u64 d;
    asm("mul.rn.f32x2 %0, %1, %2;" : "=l"(d) : "l"(a), "l"(b));
    return d;
}
__device__ __forceinline__ float f2lo(u64 v) { return __int_as_float((int)(unsigned)v); }
__device__ __forceinline__ float f2hi(u64 v) { return __int_as_float((int)(unsigned)(v >> 32)); }
__device__ __forceinline__ void ldmx4(unsigned* r, unsigned addr) {
    asm volatile("ldmatrix.sync.aligned.m8n8.x4.shared.b16 {%0,%1,%2,%3}, [%4];"
                 : "=r"(r[0]), "=r"(r[1]), "=r"(r[2]), "=r"(r[3]) : "r"(addr));
}
__device__ __forceinline__ void mma16816(float* d, const unsigned* a, const unsigned* b) {
    asm volatile("mma.sync.aligned.m16n8k16.row.col.f32.f16.f16.f32 "
                 "{%0,%1,%2,%3}, {%4,%5,%6,%7}, {%8,%9}, {%0,%1,%2,%3};"
                 : "+f"(d[0]), "+f"(d[1]), "+f"(d[2]), "+f"(d[3])
                 : "r"(a[0]), "r"(a[1]), "r"(a[2]), "r"(a[3]), "r"(b[0]), "r"(b[1]));
}
__device__ __forceinline__ void stcs2(float* p, float a, float b) {
    asm volatile("st.global.cs.v2.f32 [%0], {%1, %2};" :: "l"(p), "f"(a), "f"(b) : "memory");
}

// ===================== two-stage, warp-per-token, 2 CTAs/SM =====================
__global__ __launch_bounds__(THREADS, 2)
void ftok_kernel(const float* __restrict__ x,   float* __restrict__ out,
                 const float* __restrict__ Wg,  const float* __restrict__ bg,
                 const float* __restrict__ Wm,  int ntiles, int stride) {
    extern __shared__ char smem[];
    const unsigned sb = smem_u32(smem);
    const int tid = threadIdx.x, wid = tid >> 5, l = tid & 31;
    const int ntl = blockIdx.x & 1;       // token half (8 tokens)
    int       mt  = blockIdx.x >> 1;      // shared mt sequence with the paired CTA
    const int tglob = ntl * TPC + wid;    // this warp's global token
    const int m1  = tid >> 3;             // stage1 row (0..31)
    const int dg8 = tid & 7;              // stage1 d-group of 8 d's

    // ---- init: stage this CTA's 8 Wg token blocks (fp32->fp16) into y region ----
    // 256 rows x 16 float4 = 4096 float4
    #pragma unroll
    for (int i = 0; i < 16; i++) {
        int u = tid + i * THREADS;
        int row = u >> 4, j4 = u & 15;    // row = local (t_local*32+n)
        float4 v = *(const float4*)(Wg + ((size_t)(ntl * 256 + row)) * 64 + j4 * 4);
        __half2 h0 = __float22half2_rn(make_float2(v.x, v.y));
        __half2 h1 = __float22half2_rn(make_float2(v.z, v.w));
        *(uint2*)(smem + SM_Y + row * PITCH + j4 * 8) =
            make_uint2(*(unsigned*)&h0, *(unsigned*)&h1);
    }
    // dup-packed Wm for this CTA's 8 tokens (32 u64)
    if (tid < 32) {
        unsigned w = __float_as_uint(Wm[ntl * 32 + tid]);
        ((u64*)(smem + SM_WMD))[tid] = ((u64)w << 32) | w;
    }

    // ---- register-resident beff for this warp's 8 output columns ----
    float2 be[4];
    {
        float s = Wm[tglob * 4] + Wm[tglob * 4 + 1] + Wm[tglob * 4 + 2] + Wm[tglob * 4 + 3];
        #pragma unroll
        for (int j = 0; j < 4; j++) {
            float2 b = *(const float2*)(bg + tglob * 32 + j * 8 + 2 * (l & 3));
            be[j] = make_float2(s * b.x, s * b.y);
        }
    }

    // ---- prologue LDG: x tile mt (row m1, d's dg8*8..+7, all 4 c) ----
    float4 xr[8];
    {
        const float* xrow = x + ((size_t)(mt * MTILE + m1)) * KDIM + dg8 * 8;
        #pragma unroll
        for (int c = 0; c < 4; c++) {
            xr[c * 2]     = *(const float4*)(xrow + c * 64);
            xr[c * 2 + 1] = *(const float4*)(xrow + c * 64 + 4);
        }
    }

    __syncthreads();  // Wg staged & Wm dup visible

    // ---- extract register-resident B fragments (token t_local = wid), once ----
    unsigned bf[4][8];                    // [ks][2 regs x 4 n8-tiles]
    {
        const unsigned b_lane = sb + SM_Y + (unsigned)(wid * TTOK) +
            (unsigned)(((l & 7) + ((l >> 4) & 1) * 8) * PITCH + ((l >> 3) & 1) * 16);
        #pragma unroll
        for (int ks = 0; ks < 4; ks++) {
            ldmx4(&bf[ks][0], b_lane + (unsigned)(ks * 32));                 // n8 0,1
            ldmx4(&bf[ks][4], b_lane + (unsigned)(16 * PITCH + ks * 32));    // n8 2,3
        }
    }
    __syncthreads();  // all warps done reading Wg; y-region reusable

    const ulonglong2* wmd = (const ulonglong2*)(smem + SM_WMD);
    const unsigned ysts = (unsigned)(m1 * PITCH + dg8 * 16);
    const unsigned a_lane = sb + SM_Y + (unsigned)(wid * TTOK) +
        (unsigned)((l & 15) * PITCH + (l >> 4) * 16);

    // ---- stage1: y[m1][this CTA's 8 tokens][dg8*8..+7] -> buffer b (fp16, STS.128) ----
    auto stage1 = [&](int b) {
        const u64* xp = (const u64*)xr;       // xp[c*4+p] = d-pair p of channel c
        #pragma unroll
        for (int tt = 0; tt < TPC; tt++) {
            ulonglong2 m01 = wmd[tt * 2], m23 = wmd[tt * 2 + 1];
            u64 a0 = fmul2(m01.x, xp[0]);
            u64 a1 = fmul2(m01.x, xp[1]);
            u64 a2 = fmul2(m01.x, xp[2]);
            u64 a3 = fmul2(m01.x, xp[3]);
            a0 = ffma2(m01.y, xp[4], a0);   a1 = ffma2(m01.y, xp[5], a1);
            a2 = ffma2(m01.y, xp[6], a2);   a3 = ffma2(m01.y, xp[7], a3);
            a0 = ffma2(m23.x, xp[8], a0);   a1 = ffma2(m23.x, xp[9], a1);
            a2 = ffma2(m23.x, xp[10], a2);  a3 = ffma2(m23.x, xp[11], a3);
            a0 = ffma2(m23.y, xp[12], a0);  a1 = ffma2(m23.y, xp[13], a1);
            a2 = ffma2(m23.y, xp[14], a2);  a3 = ffma2(m23.y, xp[15], a3);
            __half2 h0 = __float22half2_rn(make_float2(f2lo(a0), f2hi(a0)));
            __half2 h1 = __float22half2_rn(make_float2(f2lo(a1), f2hi(a1)));
            __half2 h2 = __float22half2_rn(make_float2(f2lo(a2), f2hi(a2)));
            __half2 h3 = __float22half2_rn(make_float2(f2lo(a3), f2hi(a3)));
            *(uint4*)(smem + SM_Y + b * YBUF + tt * TTOK + ysts) =
                make_uint4(*(unsigned*)&h0, *(unsigned*)&h1,
                           *(unsigned*)&h2, *(unsigned*)&h3);
        }
    };

    stage1(0);
    // prefetch x tile mt+stride
    {
        int nmt = mt + stride;
        if (nmt < ntiles) {
            const float* xrow = x + ((size_t)(nmt * MTILE + m1)) * KDIM + dg8 * 8;
            #pragma unroll
            for (int c = 0; c < 4; c++) {
                xr[c * 2]     = *(const float4*)(xrow + c * 64);
                xr[c * 2 + 1] = *(const float4*)(xrow + c * 64 + 4);
            }
        }
    }
    __syncthreads();  // y[0] ready

    int buf = 0;
    for (; mt < ntiles; mt += stride) {
        // ---- stage2: token tglob, [32m x 32n, K=64], B in registers ----
        float acc[2][4][4];
        #pragma unroll
        for (int mg = 0; mg < 2; mg++)
            #pragma unroll
            for (int j = 0; j < 4; j++)
                #pragma unroll
                for (int q = 0; q < 4; q++) acc[mg][j][q] = 0.f;

        const unsigned ab = a_lane + (unsigned)(buf * YBUF);
        #pragma unroll
        for (int mg = 0; mg < 2; mg++) {
            #pragma unroll
            for (int ks = 0; ks < 4; ks++) {
                unsigned ah[4];
                ldmx4(ah, ab + (unsigned)(mg * 16 * PITCH + ks * 32));
                #pragma unroll
                for (int j = 0; j < 4; j++)
                    mma16816(acc[mg][j], ah, &bf[ks][2 * j]);
            }
        }

        // ---- epilogue: bias + relu, streaming stores ----
        #pragma unroll
        for (int mg = 0; mg < 2; mg++) {
            const int r0 = mt * MTILE + mg * 16 + (l >> 2);
            #pragma unroll
            for (int j = 0; j < 4; j++) {
                int col = tglob * 32 + j * 8 + 2 * (l & 3);
                float* p0 = out + (size_t)r0 * NDIM + col;
                stcs2(p0,
                      fmaxf(acc[mg][j][0] + be[j].x, 0.f),
                      fmaxf(acc[mg][j][1] + be[j].y, 0.f));
                stcs2(p0 + 8 * NDIM,
                      fmaxf(acc[mg][j][2] + be[j].x, 0.f),
                      fmaxf(acc[mg][j][3] + be[j].y, 0.f));
            }
        }

        // ---- stage1 for tile mt+stride into other buffer; prefetch mt+2*stride ----
        {
            int nmt = mt + stride;
            if (nmt < ntiles) {
                stage1(buf ^ 1);
                int pmt = nmt + stride;
                if (pmt < ntiles) {
                    const float* xrow = x + ((size_t)(pmt * MTILE + m1)) * KDIM + dg8 * 8;
                    #pragma unroll
                    for (int c = 0; c < 4; c++) {
                        xr[c * 2]     = *(const float4*)(xrow + c * 64);
                        xr[c * 2 + 1] = *(const float4*)(xrow + c * 64 + 4);
                    }
                }
            }
        }

        __syncthreads();  // y[buf^1] ready; y[buf] free
        buf ^= 1;
    }
}

// ===================== launch =====================
extern "C" void kernel_launch(void* const* d_in, const int* in_sizes, int n_in,
                              void* d_out, int out_size) {
    const float* x  = (const float*)d_in[0];
    const float* Wg = (const float*)d_in[1];
    const float* bg = (const float*)d_in[2];
    const float* Wm = (const float*)d_in[3];
    float* out = (float*)d_out;

    const int B      = in_sizes[0] / KDIM;   // 32768
    const int ntiles = B / MTILE;            // 1024

    cudaFuncSetAttribute(ftok_kernel,
                         cudaFuncAttributeMaxDynamicSharedMemorySize, SMEM_TOTAL);

    int dev = 0, sms = 148;
    cudaGetDevice(&dev);
    cudaDeviceGetAttribute(&sms, cudaDevAttrMultiProcessorCount, dev);
    int grid = 2 * sms;                      // 2 CTAs/SM, paired on mt, split by token half
    if (grid > 2 * ntiles) grid = 2 * ntiles;
    int stride = grid >> 1;

    ftok_kernel<<<grid, THREADS, SMEM_TOTAL>>>(x, out, Wg, bg, Wm, ntiles, stride);
}

// round 16
// speedup vs baseline: 1.0845x; 1.0845x over previous
#include <cuda_runtime.h>
#include <cuda_fp16.h>

// ===================== problem constants =====================
#define KDIM    256            // x row: c*64+d
#define NDIM    512            // t*32+o
#define MTILE   32
#define THREADS 512

// ===================== smem layout =====================
#define PITCH   144                        // 64 fp16 (128B) + 16B pad (validated conflict-free)
#define TTOK    (32 * PITCH)               // 4608 per token sub-tile (32 rows)
#define YBUF    (16 * TTOK)                // 73728 per y buffer; Wg staged here at init
#define SM_Y    0                          // 2 buffers: 147456
#define SM_WMD  (2 * YBUF)                 // dup-packed Wm: 16*4 u64 = 512
#define SMEM_TOTAL (SM_WMD + 512 + 128)    // 148096 (1 CTA/SM)

typedef unsigned long long u64;

// ===================== PTX helpers (validated mappings) =====================
__device__ __forceinline__ unsigned smem_u32(const void* p) {
    unsigned a;
    asm("{ .reg .u64 t; cvta.to.shared.u64 t, %1; cvt.u32.u64 %0, t; }" : "=r"(a) : "l"(p));
    return a;
}
__device__ __forceinline__ u64 ffma2(u64 a, u64 b, u64 c) {
    u64 d;
    asm("fma.rn.f32x2 %0, %1, %2, %3;" : "=l"(d) : "l"(a), "l"(b), "l"(c));
    return d;
}
__device__ __forceinline__ u64 fmul2(u64 a, u64 b) {
    u64 d;
    asm("mul.rn.f32x2 %0, %1, %2;" : "=l"(d) : "l"(a), "l"(b));
    return d;
}
__device__ __forceinline__ float f2lo(u64 v) { return __int_as_float((int)(unsigned)v); }
__device__ __forceinline__ float f2hi(u64 v) { return __int_as_float((int)(unsigned)(v >> 32)); }
__device__ __forceinline__ void ldmx4(unsigned* r, unsigned addr) {
    asm volatile("ldmatrix.sync.aligned.m8n8.x4.shared.b16 {%0,%1,%2,%3}, [%4];"
                 : "=r"(r[0]), "=r"(r[1]), "=r"(r[2]), "=r"(r[3]) : "r"(addr));
}
__device__ __forceinline__ void mma16816(float* d, const unsigned* a, const unsigned* b) {
    asm volatile("mma.sync.aligned.m16n8k16.row.col.f32.f16.f16.f32 "
                 "{%0,%1,%2,%3}, {%4,%5,%6,%7}, {%8,%9}, {%0,%1,%2,%3};"
                 : "+f"(d[0]), "+f"(d[1]), "+f"(d[2]), "+f"(d[3])
                 : "r"(a[0]), "r"(a[1]), "r"(a[2]), "r"(a[3]), "r"(b[0]), "r"(b[1]));
}
__device__ __forceinline__ void stcs2(float* p, float a, float b) {
    asm volatile("st.global.cs.v2.f32 [%0], {%1, %2};" :: "l"(p), "f"(a), "f"(b) : "memory");
}

// ===================== single kernel, two-stage, warp-per-token =====================
__global__ __launch_bounds__(THREADS, 1)
void ftok_kernel(const float* __restrict__ x,   float* __restrict__ out,
                 const float* __restrict__ Wg,  const float* __restrict__ bg,
                 const float* __restrict__ Wm,  int ntiles, int stride) {
    extern __shared__ char smem[];
    const unsigned sb = smem_u32(smem);
    const int tid = threadIdx.x, wid = tid >> 5, l = tid & 31;
    const int t  = wid;                   // warp owns token t (stage2)
    const int m1 = tid >> 4;              // stage1 row (0..31)
    const int dg = tid & 15;              // stage1 d-group (4 d's)
    int mt = blockIdx.x;

    // ---- init: stage Wg (fp32->fp16) into y-region temporarily, pitch 144 ----
    #pragma unroll
    for (int i = 0; i < 16; i++) {
        int u = tid + i * THREADS;
        int row = u >> 4, j4 = u & 15;
        float4 v = *(const float4*)(Wg + (size_t)row * 64 + j4 * 4);
        __half2 h0 = __float22half2_rn(make_float2(v.x, v.y));
        __half2 h1 = __float22half2_rn(make_float2(v.z, v.w));
        *(uint2*)(smem + SM_Y + row * PITCH + j4 * 8) =
            make_uint2(*(unsigned*)&h0, *(unsigned*)&h1);
    }
    if (tid < 64) {
        unsigned w = __float_as_uint(Wm[tid]);
        ((u64*)(smem + SM_WMD))[tid] = ((u64)w << 32) | w;
    }

    // ---- register-resident beff for this warp's 8 output columns ----
    float2 be[4];
    {
        float s = Wm[t * 4] + Wm[t * 4 + 1] + Wm[t * 4 + 2] + Wm[t * 4 + 3];
        #pragma unroll
        for (int j = 0; j < 4; j++) {
            float2 b = *(const float2*)(bg + t * 32 + j * 8 + 2 * (l & 3));
            be[j] = make_float2(s * b.x, s * b.y);
        }
    }

    // ---- prologue LDG: x tile mt into regs ----
    float4 xr[4];
    {
        const float* xrow = x + ((size_t)(mt * MTILE + m1)) * KDIM + dg * 4;
        #pragma unroll
        for (int c = 0; c < 4; c++) xr[c] = *(const float4*)(xrow + c * 64);
    }

    __syncthreads();  // Wg staged & Wm dup visible

    // ---- extract register-resident B fragments (token t), once ----
    unsigned bf[4][8];                    // [ks][2 regs x 4 n8-tiles]
    {
        const unsigned b_lane = sb + SM_Y + (unsigned)(t * TTOK) +
            (unsigned)(((l & 7) + ((l >> 4) & 1) * 8) * PITCH + ((l >> 3) & 1) * 16);
        #pragma unroll
        for (int ks = 0; ks < 4; ks++) {
            ldmx4(&bf[ks][0], b_lane + (unsigned)(ks * 32));                 // n8 0,1
            ldmx4(&bf[ks][4], b_lane + (unsigned)(16 * PITCH + ks * 32));    // n8 2,3
        }
    }
    __syncthreads();  // all warps done reading Wg; y-region reusable

    const ulonglong2* wmd = (const ulonglong2*)(smem + SM_WMD);
    const unsigned ysts = (unsigned)(m1 * PITCH + dg * 8);
    const unsigned a_lane = sb + SM_Y + (unsigned)(t * TTOK) +
        (unsigned)((l & 15) * PITCH + (l >> 4) * 16);

    // ---- stage1: y[m1][*][dg*4..+3] for all 16 tokens -> buffer b (fp16) ----
    auto stage1 = [&](int b) {
        const u64* xp = (const u64*)xr;       // xp[2c], xp[2c+1] = d pairs
        #pragma unroll
        for (int tt = 0; tt < 16; tt++) {
            ulonglong2 m01 = wmd[tt * 2], m23 = wmd[tt * 2 + 1];
            u64 a0 = fmul2(m01.x, xp[0]);
            u64 a1 = fmul2(m01.x, xp[1]);
            a0 = ffma2(m01.y, xp[2], a0);  a1 = ffma2(m01.y, xp[3], a1);
            a0 = ffma2(m23.x, xp[4], a0);  a1 = ffma2(m23.x, xp[5], a1);
            a0 = ffma2(m23.y, xp[6], a0);  a1 = ffma2(m23.y, xp[7], a1);
            __half2 h0 = __float22half2_rn(make_float2(f2lo(a0), f2hi(a0)));
            __half2 h1 = __float22half2_rn(make_float2(f2lo(a1), f2hi(a1)));
            *(uint2*)(smem + SM_Y + b * YBUF + tt * TTOK + ysts) =
                make_uint2(*(unsigned*)&h0, *(unsigned*)&h1);
        }
    };

    stage1(0);                 // y(tile0) -> buf0
    // xr <- x(tile mt+stride)
    {
        int nmt = mt + stride;
        if (nmt < ntiles) {
            const float* xrow = x + ((size_t)(nmt * MTILE + m1)) * KDIM + dg * 4;
            #pragma unroll
            for (int c = 0; c < 4; c++) xr[c] = *(const float4*)(xrow + c * 64);
        }
    }
    __syncthreads();  // y[0] ready

    int buf = 0;
    for (; mt < ntiles; mt += stride) {
        // ---- stage1 FIRST: y(mt+stride) -> buf^1 (pure fma; desyncs warps) ----
        {
            int nmt = mt + stride;
            if (nmt < ntiles) stage1(buf ^ 1);
        }

        // ---- prefetch x(mt+2*stride) (LDG hides under stage2) ----
        {
            int pmt = mt + 2 * stride;
            if (pmt < ntiles) {
                const float* xrow = x + ((size_t)(pmt * MTILE + m1)) * KDIM + dg * 4;
                #pragma unroll
                for (int c = 0; c < 4; c++) xr[c] = *(const float4*)(xrow + c * 64);
            }
        }

        // ---- stage2: token t, [32m x 32n, K=64], B in registers, batched LDSM ----
        float acc[2][4][4];
        #pragma unroll
        for (int mg = 0; mg < 2; mg++)
            #pragma unroll
            for (int j = 0; j < 4; j++)
                #pragma unroll
                for (int q = 0; q < 4; q++) acc[mg][j][q] = 0.f;

        const unsigned ab = a_lane + (unsigned)(buf * YBUF);
        #pragma unroll
        for (int mg = 0; mg < 2; mg++) {
            unsigned ah[4][4];
            #pragma unroll
            for (int ks = 0; ks < 4; ks++)      // 4 independent LDSM (MLP)
                ldmx4(ah[ks], ab + (unsigned)(mg * 16 * PITCH + ks * 32));
            #pragma unroll
            for (int ks = 0; ks < 4; ks++)
                #pragma unroll
                for (int j = 0; j < 4; j++)
                    mma16816(acc[mg][j], ah[ks], &bf[ks][2 * j]);
        }

        // ---- epilogue: bias + relu, streaming stores ----
        #pragma unroll
        for (int mg = 0; mg < 2; mg++) {
            const int r0 = mt * MTILE + mg * 16 + (l >> 2);
            #pragma unroll
            for (int j = 0; j < 4; j++) {
                int col = t * 32 + j * 8 + 2 * (l & 3);
                float* p0 = out + (size_t)r0 * NDIM + col;
                stcs2(p0,
                      fmaxf(acc[mg][j][0] + be[j].x, 0.f),
                      fmaxf(acc[mg][j][1] + be[j].y, 0.f));
                stcs2(p0 + 8 * NDIM,
                      fmaxf(acc[mg][j][2] + be[j].x, 0.f),
                      fmaxf(acc[mg][j][3] + be[j].y, 0.f));
            }
        }

        __syncthreads();  // y[buf^1] ready; y[buf] free
        buf ^= 1;
    }
}

// ===================== launch =====================
extern "C" void kernel_launch(void* const* d_in, const int* in_sizes, int n_in,
                              void* d_out, int out_size) {
    const float* x  = (const float*)d_in[0];
    const float* Wg = (const float*)d_in[1];
    const float* bg = (const float*)d_in[2];
    const float* Wm = (const float*)d_in[3];
    float* out = (float*)d_out;

    const int B      = in_sizes[0] / KDIM;   // 32768
    const int ntiles = B / MTILE;            // 1024

    cudaFuncSetAttribute(ftok_kernel,
                         cudaFuncAttributeMaxDynamicSharedMemorySize, SMEM_TOTAL);

    int dev = 0, sms = 148;
    cudaGetDevice(&dev);
    cudaDeviceGetAttribute(&sms, cudaDevAttrMultiProcessorCount, dev);
    int grid = sms < ntiles ? sms : ntiles;

    ftok_kernel<<<grid, THREADS, SMEM_TOTAL>>>(x, out, Wg, bg, Wm, ntiles, grid);
}